// round 16
// speedup vs baseline: 3.0677x; 1.0183x over previous
#include <cuda_runtime.h>
#include <cuda_fp16.h>
#include <math.h>
#include <stdint.h>

#define SQ 4096
#define CHN 1280
#define CC 768
#define NHEAD 8
#define HD 160
#define NCTX 77
#define NCTXP 80
#define NST 9
#define NSTR 8
#define LLOC 257
#define LLOCP 272
#define PSTU 44
#define PLU 140
#define VLU 140
#define SMEM3 (3 * 2048 * 2 * 4)

// ---------------- scratch ----------------
__device__ __align__(256) __half g_hsH[2 * SQ * CHN];
__device__ __align__(256) __half g_ctxH[NST * NCTX * CC];
__device__ __align__(256) __half g_lfH[NSTR * LLOC * CC];
__device__ __align__(256) __half g_q2[2 * SQ * CHN];
__device__ __align__(256) __half g_k[NST * NCTX * CHN];
__device__ __align__(256) __half g_v[NST * NCTX * CHN];
__device__ __align__(256) __half g_kg[NSTR * NCTX * CHN];
__device__ __align__(256) __half g_vg[NSTR * NCTX * CHN];
__device__ __align__(256) __half g_kl[NSTR * LLOC * CHN];
__device__ __align__(256) __half g_vl[NSTR * LLOC * CHN];
__device__ __align__(256) __half g_WqT[CHN * CHN];
__device__ __align__(256) __half g_WkT[CHN * CC];
__device__ __align__(256) __half g_WvT[CHN * CC];
__device__ __align__(256) __half g_WkgT[CHN * CC];
__device__ __align__(256) __half g_WvgT[CHN * CC];
__device__ __align__(256) __half g_WklT[CHN * CC];
__device__ __align__(256) __half g_WvlT[CHN * CC];
__device__ __align__(256) __half g_WoutT[CHN * CHN];
__device__ __align__(256) __half g_vT[NST * CHN * NCTXP];
__device__ __align__(256) __half g_vlT[NSTR * CHN * LLOCP];
__device__ __align__(256) __half g_pre[NST * SQ * CHN];
__device__ __align__(256) __half g_mix[SQ * CHN];
__device__ float g_mraw[NSTR * NHEAD * SQ];
__device__ float g_mmax[NSTR];
__device__ float g_sumw[SQ];

__device__ const __half* d_Ap[16];
__device__ const __half* d_Bp[16];
__device__ void*         d_Cp[16];
__device__ int           d_Mt[16];

// ---------------- streams/events ----------------
struct StreamInit {
    cudaStream_t sA, sB, sC;
    cudaEvent_t evRoot, ev1, ev2, ev3, evG, evO7, evW;
    StreamInit() {
        cudaStreamCreateWithFlags(&sA, cudaStreamNonBlocking);
        cudaStreamCreateWithFlags(&sB, cudaStreamNonBlocking);
        cudaStreamCreateWithFlags(&sC, cudaStreamNonBlocking);
        cudaEventCreateWithFlags(&evRoot, cudaEventDisableTiming);
        cudaEventCreateWithFlags(&ev1, cudaEventDisableTiming);
        cudaEventCreateWithFlags(&ev2, cudaEventDisableTiming);
        cudaEventCreateWithFlags(&ev3, cudaEventDisableTiming);
        cudaEventCreateWithFlags(&evG, cudaEventDisableTiming);
        cudaEventCreateWithFlags(&evO7, cudaEventDisableTiming);
        cudaEventCreateWithFlags(&evW, cudaEventDisableTiming);
    }
};
static StreamInit g_si;

// ---------------- helpers ----------------
__device__ __forceinline__ uint32_t pk2(float a, float b) {
    __half2 h = __halves2half2(__float2half_rn(a), __float2half_rn(b));
    return *(uint32_t*)&h;
}
__device__ __forceinline__ void cp16(void* sdst, const void* gsrc, bool p) {
    uint32_t sa = (uint32_t)__cvta_generic_to_shared(sdst);
    int sz = p ? 16 : 0;
    asm volatile("cp.async.cg.shared.global [%0], [%1], 16, %2;" :: "r"(sa), "l"(gsrc), "r"(sz));
}
#define CP_COMMIT asm volatile("cp.async.commit_group;")
#define CP_WAIT0 asm volatile("cp.async.wait_group 0;")
#define CP_WAIT1 asm volatile("cp.async.wait_group 1;")
__device__ __forceinline__ void mma16(float* c, const uint32_t* a, const uint32_t* b) {
    asm volatile(
        "mma.sync.aligned.m16n8k16.row.col.f32.f16.f16.f32 "
        "{%0,%1,%2,%3}, {%4,%5,%6,%7}, {%8,%9}, {%0,%1,%2,%3};"
        : "+f"(c[0]), "+f"(c[1]), "+f"(c[2]), "+f"(c[3])
        : "r"(a[0]), "r"(a[1]), "r"(a[2]), "r"(a[3]), "r"(b[0]), "r"(b[1]));
}
__device__ __forceinline__ void ldsm4(uint32_t* r, uint32_t addr) {
    asm volatile("ldmatrix.sync.aligned.m8n8.x4.shared.b16 {%0,%1,%2,%3}, [%4];"
                 : "=r"(r[0]), "=r"(r[1]), "=r"(r[2]), "=r"(r[3]) : "r"(addr));
}
__device__ __forceinline__ void ldsm2(uint32_t* r, uint32_t addr) {
    asm volatile("ldmatrix.sync.aligned.m8n8.x2.shared.b16 {%0,%1}, [%2];"
                 : "=r"(r[0]), "=r"(r[1]) : "r"(addr));
}
#define SWOFF(r, c) (((r) << 4) + ((((((c) >> 2) ^ (((r) >> 1) & 3))) << 2) | ((c) & 3)))

// ---------------- setup ----------------
__global__ void setup_k(float* out) {
    if (threadIdx.x == 0) {
        d_Ap[0] = g_hsH;               d_Bp[0] = g_WqT;   d_Cp[0] = g_q2;    d_Mt[0] = 2 * SQ;
        d_Ap[1] = g_ctxH;              d_Bp[1] = g_WkT;   d_Cp[1] = g_k;     d_Mt[1] = NST * NCTX;
        d_Ap[2] = g_ctxH;              d_Bp[2] = g_WvT;   d_Cp[2] = g_v;     d_Mt[2] = NST * NCTX;
        d_Ap[3] = g_ctxH + NCTX * CC;  d_Bp[3] = g_WkgT;  d_Cp[3] = g_kg;    d_Mt[3] = NSTR * NCTX;
        d_Ap[4] = g_ctxH + NCTX * CC;  d_Bp[4] = g_WvgT;  d_Cp[4] = g_vg;    d_Mt[4] = NSTR * NCTX;
        d_Ap[5] = g_lfH;               d_Bp[5] = g_WklT;  d_Cp[5] = g_kl;    d_Mt[5] = NSTR * LLOC;
        d_Ap[6] = g_lfH;               d_Bp[6] = g_WvlT;  d_Cp[6] = g_vl;    d_Mt[6] = NSTR * LLOC;
        d_Ap[7] = g_pre;               d_Bp[7] = g_WoutT; d_Cp[7] = out;     d_Mt[7] = SQ;
        d_Ap[8] = g_mix;               d_Bp[8] = g_WoutT; d_Cp[8] = out + (size_t)SQ * CHN;
        d_Mt[8] = SQ;
    }
}

// ---------------- round inputs to fp16 ----------------
__global__ void round_h(const float* __restrict__ src, __half* __restrict__ dst, long long n) {
    long long i = ((long long)blockIdx.x * blockDim.x + threadIdx.x) * 8;
    if (i + 7 < n) {
        float4 a = *(const float4*)(src + i);
        float4 b = *(const float4*)(src + i + 4);
        uint4 u;
        u.x = pk2(a.x, a.y); u.y = pk2(a.z, a.w);
        u.z = pk2(b.x, b.y); u.w = pk2(b.z, b.w);
        *(uint4*)(dst + i) = u;
    } else {
        for (long long j = i; j < n; j++) dst[j] = __float2half_rn(src[j]);
    }
}

// ---------------- transpose ----------------
template <typename TS>
__global__ void transpose_k(const TS* __restrict__ src, __half* __restrict__ dst,
                            int R, int C, int ldS, int ldD, long long sBS, long long dBS) {
    __shared__ float t[32][33];
    src += blockIdx.z * sBS;
    dst += blockIdx.z * dBS;
    int c0 = blockIdx.x << 5, r0 = blockIdx.y << 5;
    int tx = threadIdx.x, ty = threadIdx.y;
#pragma unroll
    for (int j = 0; j < 4; j++) {
        int rr = r0 + ty + j * 8, cc = c0 + tx;
        t[ty + j * 8][tx] = (rr < R && cc < C) ? (float)src[(size_t)rr * ldS + cc] : 0.f;
    }
    __syncthreads();
#pragma unroll
    for (int j = 0; j < 4; j++) {
        int cc = c0 + ty + j * 8, rr = r0 + tx;
        if (cc < C && rr < ldD)
            dst[(size_t)cc * ldD + rr] = __float2half_rn(t[tx][ty + j * 8]);
    }
}

// ---------------- batched NT fp16 GEMM (R8 core + fused output epilogue) ------
// mode bits: 1 = half output; 4 = add bias (float out); 8 = fuser normalize
__global__ void __launch_bounds__(256, 2) gemm_h(int slot, int N, int K,
                                                 int lda, int ldb, int ldc, int mode,
                                                 const float* __restrict__ bias) {
    extern __shared__ __align__(16) uint32_t smg[];
    uint32_t* As = smg;
    uint32_t* Bs = smg + 3 * 2048;
    const __half* Ab = d_Ap[slot + blockIdx.z];
    const __half* Bb = d_Bp[slot + blockIdx.z];
    void* Cm         = d_Cp[slot + blockIdx.z];
    const int M      = d_Mt[slot + blockIdx.z];
    int tid = threadIdx.x, lane = tid & 31, warp = tid >> 5;
    int mBase = blockIdx.y << 7, nBase = blockIdx.x << 7;
    int mW = (warp >> 2) << 6, nW = (warp & 3) << 5;
    float acc[4][4][4];
#pragma unroll
    for (int a = 0; a < 4; a++)
#pragma unroll
        for (int b = 0; b < 4; b++)
#pragma unroll
            for (int cI = 0; cI < 4; cI++) acc[a][b][cI] = 0.f;

    int KT = K >> 5;
    auto issue = [&](int st, int kt) {
        int k0 = kt << 5;
#pragma unroll
        for (int i = 0; i < 2; i++) {
            int idx = tid + (i << 8);
            int r = idx >> 2, cu = (idx & 3) << 2;
            int gr = mBase + r; bool pa = gr < M; if (!pa) gr = M - 1;
            cp16(&As[st * 2048 + SWOFF(r, cu)], Ab + (size_t)gr * lda + k0 + (cu << 1), pa);
            int gn = nBase + r; bool pb = gn < N; if (!pb) gn = N - 1;
            cp16(&Bs[st * 2048 + SWOFF(r, cu)], Bb + (size_t)gn * ldb + k0 + (cu << 1), pb);
        }
        CP_COMMIT;
    };
    issue(0, 0);
    issue(1, 1);

    int lrow = lane & 7;
    int lm = lane >> 3;
    int arow[4], axor[4];
#pragma unroll
    for (int mi = 0; mi < 4; mi++) {
        arow[mi] = mW + (mi << 4) + ((lm & 1) << 3) + lrow;
        axor[mi] = (arow[mi] >> 1) & 3;
    }
    int achk = lm >> 1;
    int brow[2], bxor[2];
#pragma unroll
    for (int np = 0; np < 2; np++) {
        brow[np] = nW + (np << 4) + ((lm >> 1) << 3) + lrow;
        bxor[np] = (brow[np] >> 1) & 3;
    }
    int bchk = lm & 1;
    uint32_t sbA = (uint32_t)__cvta_generic_to_shared(As);
    uint32_t sbB = (uint32_t)__cvta_generic_to_shared(Bs);

    for (int kt = 0; kt < KT; kt++) {
        if (kt + 1 < KT) { CP_WAIT1; } else { CP_WAIT0; }
        __syncthreads();
        if (kt + 2 < KT) issue((kt + 2) % 3, kt + 2);
        uint32_t stA = sbA + (kt % 3) * 8192;
        uint32_t stB = sbB + (kt % 3) * 8192;
#pragma unroll
        for (int kk = 0; kk < 2; kk++) {
            uint32_t af[4][4], bf[4][2];
#pragma unroll
            for (int mi = 0; mi < 4; mi++) {
                uint32_t au = (uint32_t)(arow[mi] << 4) + ((((kk << 1) + achk) ^ axor[mi]) << 2);
                ldsm4(af[mi], stA + (au << 2));
            }
#pragma unroll
            for (int np = 0; np < 2; np++) {
                uint32_t bu = (uint32_t)(brow[np] << 4) + ((((kk << 1) + bchk) ^ bxor[np]) << 2);
                uint32_t r4[4];
                ldsm4(r4, stB + (bu << 2));
                bf[np * 2][0] = r4[0]; bf[np * 2][1] = r4[1];
                bf[np * 2 + 1][0] = r4[2]; bf[np * 2 + 1][1] = r4[3];
            }
#pragma unroll
            for (int mi = 0; mi < 4; mi++)
#pragma unroll
                for (int ni = 0; ni < 4; ni++) mma16(acc[mi][ni], af[mi], bf[ni]);
        }
    }
#pragma unroll
    for (int mi = 0; mi < 4; mi++) {
#pragma unroll
        for (int half = 0; half < 2; half++) {
            int gm = mBase + mW + (mi << 4) + (lane >> 2) + half * 8;
            if (gm >= M) continue;
            float sw = 0.f, den = 0.f;
            if (mode & 8) { sw = g_sumw[gm]; den = 1.f / (sw + 1e-6f); }
#pragma unroll
            for (int ni = 0; ni < 4; ni++) {
                int gn = nBase + nW + (ni << 3) + ((lane & 3) << 1);
                if (gn + 1 >= N) continue;
                float v0 = acc[mi][ni][half * 2], v1 = acc[mi][ni][half * 2 + 1];
                if (mode & 1) {
                    __half* crow = (__half*)Cm + (size_t)gm * ldc;
                    *(uint32_t*)(crow + gn) = pk2(v0, v1);
                } else {
                    float* crow = (float*)Cm + (size_t)gm * ldc;
                    if (mode & 4) {
                        float b0 = bias[gn], b1 = bias[gn + 1];
                        if (mode & 8) {
                            v0 = (v0 + b0 * sw) * den;
                            v1 = (v1 + b1 * sw) * den;
                        } else {
                            v0 += b0;
                            v1 += b1;
                        }
                    }
                    crow[gn] = v0;
                    crow[gn + 1] = v1;
                }
            }
        }
    }
}

// ---------------- ELITE K/V select ----------------
__global__ void kv_select_k(const int* __restrict__ lidx) {
    int idx = blockIdx.x * 256 + threadIdx.x;
    const int tot = NSTR * NCTX * CHN / 2;
    if (idx >= tot) return;
    int st = idx / (NCTX * CHN / 2);
    if (lidx[st] >= 0) {
        ((uint32_t*)g_k)[NCTX * CHN / 2 + idx] = ((const uint32_t*)g_kg)[idx];
        ((uint32_t*)g_v)[NCTX * CHN / 2 + idx] = ((const uint32_t*)g_vg)[idx];
    }
}

// ============ fused global attention: 256-row q-tiles, 512 threads ============
// grid (16 qtiles of 256 rows, 72 bh)
__global__ void __launch_bounds__(512, 1) fused_g_k(const int* __restrict__ lidx) {
    extern __shared__ __align__(16) uint32_t smu[];
    uint32_t* qb  = smu;                       // 2 stages * 4096
    uint32_t* kb  = smu + 8192;                // 2 stages * 2048
    uint32_t* psm = smu + 12288;               // 256 * PSTU
    uint32_t* vsm = psm + 256 * PSTU;          // 160 * PSTU
    float* smx = (float*)(vsm + 160 * PSTU);   // 2 * 256
    float* ssu = smx + 512;                    // 2 * 256
    __shared__ int sidx[8];

    int bh = blockIdx.y;
    int stream = bh >> 3, h = bh & 7;
    int q0 = blockIdx.x << 8;
    int tid = threadIdx.x, lane = tid & 31, warp = tid >> 5;
    if (tid < 8) sidx[tid] = lidx[tid];

    const __half* Qb = g_q2 + (stream ? (size_t)SQ * CHN : 0) + (size_t)q0 * CHN + h * HD;
    const __half* Kb = g_k + (size_t)stream * NCTX * CHN + h * HD;
    const __half* Vt = g_vT + (size_t)stream * CHN * NCTXP + (size_t)h * HD * NCTXP;

    for (int u = tid; u < 160 * 10; u += 512) {
        int d = u / 10, c = u % 10;
        cp16(vsm + d * PSTU + c * 4, Vt + (size_t)d * NCTXP + c * 8, true);
    }
    CP_COMMIT;

    auto issueQK = [&](int st, int kt) {
        int k0 = kt << 5;
#pragma unroll
        for (int i = 0; i < 2; i++) {
            int idx = tid + (i << 9);
            int r = idx >> 2, cu = (idx & 3) << 2;
            cp16(&qb[st * 4096 + SWOFF(r, cu)], Qb + (size_t)r * CHN + k0 + (cu << 1), true);
        }
        {
            int r = tid >> 2, cu = (tid & 3) << 2;
            if (r < 128) {
                int kr = (r < NCTX) ? r : (NCTX - 1);
                cp16(&kb[st * 2048 + SWOFF(r, cu)], Kb + (size_t)kr * CHN + k0 + (cu << 1), true);
            }
        }
        CP_COMMIT;
    };
    issueQK(0, 0);

    int mW = (warp >> 1) << 5;        // 0..224
    int nWs = (warp & 1) * 40;
    int lrow = lane & 7, lm = lane >> 3;
    int aqr[2], aqx[2];
#pragma unroll
    for (int mi = 0; mi < 2; mi++) {
        aqr[mi] = mW + (mi << 4) + ((lm & 1) << 3) + lrow;
        aqx[mi] = (aqr[mi] >> 1) & 3;
    }
    int achk = lm >> 1;
    int bkr[2], bkx[2];
#pragma unroll
    for (int np = 0; np < 2; np++) {
        bkr[np] = nWs + (np << 4) + ((lm >> 1) << 3) + lrow;
        bkx[np] = (bkr[np] >> 1) & 3;
    }
    int bchk = lm & 1;
    int b2r = nWs + 32 + lrow;
    int b2x = (b2r >> 1) & 3;
    int b2c = (lane >> 3) & 1;
    uint32_t sbQ = (uint32_t)__cvta_generic_to_shared(qb);
    uint32_t sbK = (uint32_t)__cvta_generic_to_shared(kb);

    float sc[2][5][4];
#pragma unroll
    for (int a = 0; a < 2; a++)
#pragma unroll
        for (int b = 0; b < 5; b++)
#pragma unroll
            for (int c = 0; c < 4; c++) sc[a][b][c] = 0.f;

    for (int kt = 0; kt < 5; kt++) {
        if (kt < 4) { issueQK((kt + 1) & 1, kt + 1); CP_WAIT1; }
        else        { CP_WAIT0; }
        __syncthreads();
        uint32_t stQ = sbQ + (kt & 1) * 16384;
        uint32_t stK = sbK + (kt & 1) * 8192;
#pragma unroll
        for (int kk = 0; kk < 2; kk++) {
            uint32_t af[2][4], bf[5][2];
#pragma unroll
            for (int mi = 0; mi < 2; mi++) {
                uint32_t au = (uint32_t)(aqr[mi] << 4) + ((((kk << 1) + achk) ^ aqx[mi]) << 2);
                ldsm4(af[mi], stQ + (au << 2));
            }
#pragma unroll
            for (int np = 0; np < 2; np++) {
                uint32_t bu = (uint32_t)(bkr[np] << 4) + ((((kk << 1) + bchk) ^ bkx[np]) << 2);
                uint32_t r4[4];
                ldsm4(r4, stK + (bu << 2));
                bf[np * 2][0] = r4[0]; bf[np * 2][1] = r4[1];
                bf[np * 2 + 1][0] = r4[2]; bf[np * 2 + 1][1] = r4[3];
            }
            {
                uint32_t bu = (uint32_t)(b2r << 4) + ((((kk << 1) + b2c) ^ b2x) << 2);
                uint32_t r2[2];
                ldsm2(r2, stK + (bu << 2));
                bf[4][0] = r2[0]; bf[4][1] = r2[1];
            }
#pragma unroll
            for (int mi = 0; mi < 2; mi++)
#pragma unroll
                for (int ni = 0; ni < 5; ni++) mma16(sc[mi][ni], af[mi], bf[ni]);
        }
        __syncthreads();
    }

    const float scale = 0.07905694150420949f;
    int half = warp & 1;
#pragma unroll
    for (int mi = 0; mi < 2; mi++)
#pragma unroll
        for (int hf = 0; hf < 2; hf++) {
            int row = mW + mi * 16 + (lane >> 2) + hf * 8;
            float mx = -1e30f;
#pragma unroll
            for (int ni = 0; ni < 5; ni++)
#pragma unroll
                for (int c = 0; c < 2; c++) {
                    int col = nWs + ni * 8 + ((lane & 3) << 1) + c;
                    if (col < NCTX) mx = fmaxf(mx, sc[mi][ni][hf * 2 + c]);
                }
            mx = fmaxf(mx, __shfl_xor_sync(0xffffffffu, mx, 1));
            mx = fmaxf(mx, __shfl_xor_sync(0xffffffffu, mx, 2));
            if ((lane & 3) == 0) smx[half * 256 + row] = mx;
        }
    __syncthreads();
#pragma unroll
    for (int mi = 0; mi < 2; mi++)
#pragma unroll
        for (int hf = 0; hf < 2; hf++) {
            int row = mW + mi * 16 + (lane >> 2) + hf * 8;
            float m = fmaxf(smx[row], smx[256 + row]);
            float s = 0.f;
#pragma unroll
            for (int ni = 0; ni < 5; ni++)
#pragma unroll
                for (int c = 0; c < 2; c++) {
                    int col = nWs + ni * 8 + ((lane & 3) << 1) + c;
                    float e = (col < NCTX) ? __expf((sc[mi][ni][hf * 2 + c] - m) * scale) : 0.f;
                    sc[mi][ni][hf * 2 + c] = e;
                    s += e;
                }
            s += __shfl_xor_sync(0xffffffffu, s, 1);
            s += __shfl_xor_sync(0xffffffffu, s, 2);
            if ((lane & 3) == 0) ssu[half * 256 + row] = s;
        }
    __syncthreads();
#pragma unroll
    for (int mi = 0; mi < 2; mi++)
#pragma unroll
        for (int hf = 0; hf < 2; hf++) {
            int row = mW + mi * 16 + (lane >> 2) + hf * 8;
            float inv = 1.f / (ssu[row] + ssu[256 + row]);
#pragma unroll
            for (int ni = 0; ni < 5; ni++) {
                int col = nWs + ni * 8 + ((lane & 3) << 1);
                float v0 = (col < NCTX) ? sc[mi][ni][hf * 2] * inv : 0.f;
                float v1 = (col + 1 < NCTX) ? sc[mi][ni][hf * 2 + 1] * inv : 0.f;
                psm[row * PSTU + (nWs >> 1) + ni * 4 + (lane & 3)] = pk2(v0, v1);
            }
        }
    __syncthreads();

    if (stream == 0) {
        const __half* ph = (const __half*)psm;
        for (int u = tid; u < 256 * 8; u += 512) {
            int r = u >> 3, i = u & 7;
            g_mraw[((size_t)i * NHEAD + h) * SQ + q0 + r] =
                __half2float(ph[r * (2 * PSTU) + sidx[i]]);
        }
    }

    int nW = (warp & 1) * 80;
    uint32_t sbP = (uint32_t)__cvta_generic_to_shared(psm);
    uint32_t sbV = (uint32_t)__cvta_generic_to_shared(vsm);
    int apr[2];
#pragma unroll
    for (int mi = 0; mi < 2; mi++) apr[mi] = mW + (mi << 4) + ((lm & 1) << 3) + lrow;
    int aco = (lm >> 1) << 2;
    int bvr[5];
#pragma unroll
    for (int np = 0; np < 5; np++) bvr[np] = nW + (np << 4) + ((lm >> 1) << 3) + lrow;
    int bco = (lm & 1) << 2;

    float oa[2][10][4];
#pragma unroll
    for (int a = 0; a < 2; a++)
#pragma unroll
        for (int b = 0; b < 10; b++)
#pragma unroll
            for (int c = 0; c < 4; c++) oa[a][b][c] = 0.f;
#pragma unroll
    for (int kst = 0; kst < 5; kst++) {
        int ka0 = kst * 8;
        uint32_t af[2][4], bf[10][2];
#pragma unroll
        for (int mi = 0; mi < 2; mi++)
            ldsm4(af[mi], sbP + ((uint32_t)(apr[mi] * PSTU + ka0 + aco) << 2));
#pragma unroll
        for (int np = 0; np < 5; np++) {
            uint32_t r4[4];
            ldsm4(r4, sbV + ((uint32_t)(bvr[np] * PSTU + ka0 + bco) << 2));
            bf[np * 2][0] = r4[0]; bf[np * 2][1] = r4[1];
            bf[np * 2 + 1][0] = r4[2]; bf[np * 2 + 1][1] = r4[3];
        }
#pragma unroll
        for (int mi = 0; mi < 2; mi++)
#pragma unroll
            for (int ni = 0; ni < 10; ni++) mma16(oa[mi][ni], af[mi], bf[ni]);
    }
#pragma unroll
    for (int mi = 0; mi < 2; mi++)
#pragma unroll
        for (int hf = 0; hf < 2; hf++) {
            int g = q0 + mW + mi * 16 + (lane >> 2) + hf * 8;
            __half* orow = g_pre + ((size_t)stream * SQ + g) * CHN + h * HD;
#pragma unroll
            for (int ni = 0; ni < 10; ni++) {
                int col = nW + (ni << 3) + ((lane & 3) << 1);
                *(uint32_t*)(orow + col) = pk2(oa[mi][ni][hf * 2], oa[mi][ni][hf * 2 + 1]);
            }
        }
}

// ---------------- per-instance gate max ----------------
__global__ void mmax_k() {
    __shared__ float red[256];
    int i = blockIdx.x;
    float mx = 0.f;
    const float* p = g_mraw + (size_t)i * NHEAD * SQ;
    for (int idx = threadIdx.x; idx < NHEAD * SQ; idx += 256) mx = fmaxf(mx, p[idx]);
    red[threadIdx.x] = mx;
    __syncthreads();
    for (int s = 128; s > 0; s >>= 1) {
        if (threadIdx.x < s) red[threadIdx.x] = fmaxf(red[threadIdx.x], red[threadIdx.x + s]);
        __syncthreads();
    }
    if (threadIdx.x == 0) g_mmax[i] = red[0];
}

// ============ fully fused local attention: 128-row q-tiles (R15, proven) ======
__global__ void __launch_bounds__(256) fused_l2_k() {
    extern __shared__ __align__(16) uint32_t smu[];
    uint32_t* plm = smu;
    uint32_t* vsm = smu + 128 * PLU;
    float* smx = (float*)(smu + 128 * PLU + 160 * VLU);
    float* ssu = smx + 256;

    int z = blockIdx.y;
    int inst = z >> 3, h = z & 7;
    int q0 = blockIdx.x << 7;
    int tid = threadIdx.x, lane = tid & 31, warp = tid >> 5;

    const __half* Qb  = g_q2 + (size_t)SQ * CHN + (size_t)q0 * CHN + h * HD;
    const __half* Klb = g_kl + (size_t)inst * LLOC * CHN + h * HD;
    const __half* Vt  = g_vlT + (size_t)inst * CHN * LLOCP + (size_t)h * HD * LLOCP;

    uint32_t* strm = vsm;
    auto issueQK = [&](int st, int kt) {
        int k0 = kt << 5;
        uint32_t* base = strm + st * 6656;
#pragma unroll
        for (int i = 0; i < 2; i++) {
            int idx = tid + (i << 8);
            int r = idx >> 2, cu = (idx & 3) << 2;
            cp16(base + SWOFF(r, cu), Qb + (size_t)r * CHN + k0 + (cu << 1), true);
        }
        for (int u = tid; u < 1152; u += 256) {
            int r = u >> 2, cu = (u & 3) << 2;
            int kr = (r < LLOC) ? r : (LLOC - 1);
            cp16(base + 2048 + SWOFF(r, cu), Klb + (size_t)kr * CHN + k0 + (cu << 1), true);
        }
        CP_COMMIT;
    };
    issueQK(0, 0);

    int mW2 = (warp >> 1) << 5;
    int nW4 = (warp & 1) * 144;
    int lrow = lane & 7, lm = lane >> 3;
    int aqr[2], aqx[2];
#pragma unroll
    for (int mi = 0; mi < 2; mi++) {
        aqr[mi] = mW2 + (mi << 4) + ((lm & 1) << 3) + lrow;
        aqx[mi] = (aqr[mi] >> 1) & 3;
    }
    int achk = lm >> 1;
    int bkr[9], bkx[9];
#pragma unroll
    for (int np = 0; np < 9; np++) {
        bkr[np] = nW4 + (np << 4) + ((lm >> 1) << 3) + lrow;
        bkx[np] = (bkr[np] >> 1) & 3;
    }
    int bchk = lm & 1;
    uint32_t sbS = (uint32_t)__cvta_generic_to_shared(strm);

    float sc[2][18][4];
#pragma unroll
    for (int a = 0; a < 2; a++)
#pragma unroll
        for (int b = 0; b < 18; b++)
#pragma unroll
            for (int c = 0; c < 4; c++) sc[a][b][c] = 0.f;

    for (int kt = 0; kt < 5; kt++) {
        if (kt < 4) { issueQK((kt + 1) & 1, kt + 1); CP_WAIT1; }
        else        { CP_WAIT0; }
        __syncthreads();
        uint32_t stQ = sbS + (kt & 1) * 26624;
        uint32_t stK = stQ + 8192;
#pragma unroll
        for (int kk = 0; kk < 2; kk++) {
            uint32_t af[2][4], bf[18][2];
#pragma unroll
            for (int mi = 0; mi < 2; mi++) {
                uint32_t au = (uint32_t)(aqr[mi] << 4) + ((((kk << 1) + achk) ^ aqx[mi]) << 2);
                ldsm4(af[mi], stQ + (au << 2));
            }
#pragma unroll
            for (int np = 0; np < 9; np++) {
                uint32_t bu = (uint32_t)(bkr[np] << 4) + ((((kk << 1) + bchk) ^ bkx[np]) << 2);
                uint32_t r4[4];
                ldsm4(r4, stK + (bu << 2));
                bf[np * 2][0] = r4[0]; bf[np * 2][1] = r4[1];
                bf[np * 2 + 1][0] = r4[2]; bf[np * 2 + 1][1] = r4[3];
            }
#pragma unroll
            for (int mi = 0; mi < 2; mi++)
#pragma unroll
                for (int ni = 0; ni < 18; ni++) mma16(sc[mi][ni], af[mi], bf[ni]);
        }
        __syncthreads();
    }

    for (int u = tid; u < 160 * 34; u += 256) {
        int d = u / 34, c = u % 34;
        cp16(vsm + d * VLU + c * 4, Vt + (size_t)d * LLOCP + c * 8, true);
    }
    CP_COMMIT;

    const float scale = 0.07905694150420949f;
    float gden = 0.5f / g_mmax[inst];
#pragma unroll
    for (int mi = 0; mi < 2; mi++)
#pragma unroll
        for (int hf = 0; hf < 2; hf++) {
            int row = mW2 + mi * 16 + (lane >> 2) + hf * 8;
            float mx = -1e30f;
#pragma unroll
            for (int ni = 0; ni < 18; ni++)
#pragma unroll
                for (int c = 0; c < 2; c++) {
                    int col = nW4 + ni * 8 + ((lane & 3) << 1) + c;
                    if (col < LLOC) mx = fmaxf(mx, sc[mi][ni][hf * 2 + c]);
                }
            mx = fmaxf(mx, __shfl_xor_sync(0xffffffffu, mx, 1));
            mx = fmaxf(mx, __shfl_xor_sync(0xffffffffu, mx, 2));
            if ((lane & 3) == 0) smx[row * 2 + (warp & 1)] = mx;
        }
    __syncthreads();
#pragma unroll
    for (int mi = 0; mi < 2; mi++)
#pragma unroll
        for (int hf = 0; hf < 2; hf++) {
            int row = mW2 + mi * 16 + (lane >> 2) + hf * 8;
            float m = fmaxf(smx[row * 2], smx[row * 2 + 1]);
            float s = 0.f;
#pragma unroll
            for (int ni = 0; ni < 18; ni++)
#pragma unroll
                for (int c = 0; c < 2; c++) {
                    int col = nW4 + ni * 8 + ((lane & 3) << 1) + c;
                    float e = (col < LLOC) ? __expf((sc[mi][ni][hf * 2 + c] - m) * scale) : 0.f;
                    sc[mi][ni][hf * 2 + c] = e;
                    s += e;
                }
            s += __shfl_xor_sync(0xffffffffu, s, 1);
            s += __shfl_xor_sync(0xffffffffu, s, 2);
            if ((lane & 3) == 0) ssu[row * 2 + (warp & 1)] = s;
        }
    __syncthreads();
#pragma unroll
    for (int mi = 0; mi < 2; mi++)
#pragma unroll
        for (int hf = 0; hf < 2; hf++) {
            int row = mW2 + mi * 16 + (lane >> 2) + hf * 8;
            float s = ssu[row * 2] + ssu[row * 2 + 1];
            float f = g_mraw[(size_t)z * SQ + q0 + row] * gden / s;
#pragma unroll
            for (int ni = 0; ni < 18; ni++) {
                int ucol = (nW4 >> 1) + ni * 4 + (lane & 3);
                if (ucol < 136)
                    plm[row * PLU + ucol] = pk2(sc[mi][ni][hf * 2] * f, sc[mi][ni][hf * 2 + 1] * f);
            }
        }
    CP_WAIT0;
    __syncthreads();

    int nW = (warp & 1) * 80;
    uint32_t sbP = (uint32_t)__cvta_generic_to_shared(plm);
    uint32_t sbV = (uint32_t)__cvta_generic_to_shared(vsm);
    int apr[2];
#pragma unroll
    for (int mi = 0; mi < 2; mi++) apr[mi] = mW2 + (mi << 4) + ((lm & 1) << 3) + lrow;
    int aco = (lm >> 1) << 2;
    int bvr[5];
#pragma unroll
    for (int np = 0; np < 5; np++) bvr[np] = nW + (np << 4) + ((lm >> 1) << 3) + lrow;
    int bco = (lm & 1) << 2;

    float oa[2][10][4];
#pragma unroll
    for (int a = 0; a < 2; a++)
#pragma unroll
        for (int b = 0; b < 10; b++)
#pragma unroll
            for (int c = 0; c < 4; c++) oa[a][b][c] = 0.f;

#pragma unroll 1
    for (int ch = 0; ch < 17; ch++) {
        int ka0 = ch * 8;
        uint32_t af[2][4], bf[10][2];
#pragma unroll
        for (int mi = 0; mi < 2; mi++)
            ldsm4(af[mi], sbP + ((uint32_t)(apr[mi] * PLU + ka0 + aco) << 2));
#pragma unroll
        for (int np = 0; np < 5; np++) {
            uint32_t r4[4];
            ldsm4(r4, sbV + ((uint32_t)(bvr[np] * VLU + ka0 + bco) << 2));
            bf[np * 2][0] = r4[0]; bf[np * 2][1] = r4[1];
            bf[np * 2 + 1][0] = r4[2]; bf[np * 2 + 1][1] = r4[3];
        }
#pragma unroll
        for (int mi = 0; mi < 2; mi++)
#pragma unroll
            for (int ni = 0; ni < 10; ni++) mma16(oa[mi][ni], af[mi], bf[ni]);
    }

#pragma unroll
    for (int mi = 0; mi < 2; mi++)
#pragma unroll
        for (int hf = 0; hf < 2; hf++) {
            int g = q0 + mW2 + mi * 16 + (lane >> 2) + hf * 8;
            __half* prow = g_pre + ((size_t)(inst + 1) * SQ + g) * CHN + h * HD;
#pragma unroll
            for (int ni = 0; ni < 10; ni++) {
                int col = nW + (ni << 3) + ((lane & 3) << 1);
                __half2 old = *(__half2*)(prow + col);
                float o0 = 0.5f * __half2float(old.x) + oa[mi][ni][hf * 2];
                float o1 = 0.5f * __half2float(old.y) + oa[mi][ni][hf * 2 + 1];
                *(uint32_t*)(prow + col) = pk2(o0, o1);
            }
        }
}

// ---------------- fuser premix ----------------
__global__ void premix_k(const float* __restrict__ bbox) {
    int s = blockIdx.x;
    int y = s >> 6, x = s & 63;
    float wgt[8];
    wgt[0] = 1.f;
    float sw = 1.f;
    const int off[4] = {3, 4, 11, 12};
#pragma unroll
    for (int i = 0; i < 7; i++) {
        float wmin = floorf(1024.f * bbox[i * 4 + 0]);
        float hmin = floorf(1024.f * bbox[i * 4 + 1]);
        float wmax = floorf(1024.f * bbox[i * 4 + 2]);
        float hmax = floorf(1024.f * bbox[i * 4 + 3]);
        float R = 0.f, Cv = 0.f;
#pragma unroll
        for (int j = 0; j < 4; j++) {
            float yy = (float)(16 * y + off[j]);
            float xx = (float)(16 * x + off[j]);
            if (yy >= hmin && yy < hmax) R += 0.25f;
            if (xx >= wmin && xx < wmax) Cv += 0.25f;
        }
        float g = 10.f * R * Cv;
        wgt[i + 1] = g;
        sw += g;
    }
    if (threadIdx.x == 0) g_sumw[s] = sw;
    for (int c = threadIdx.x; c < CHN; c += 256) {
        float acc = 0.f;
#pragma unroll
        for (int j = 0; j < 8; j++)
            acc += wgt[j] * __half2float(g_pre[((size_t)(1 + j) * SQ + s) * CHN + c]);
        g_mix[(size_t)s * CHN + c] = __float2half_rn(acc);
    }
}

// ---------------- launch ----------------
extern "C" void kernel_launch(void* const* d_in, const int* in_sizes, int n_in,
                              void* d_out, int out_size) {
    const float* hs   = (const float*)d_in[0];
    const float* ctx  = (const float*)d_in[1];
    const float* lf   = (const float*)d_in[2];
    const float* bbox = (const float*)d_in[3];
    const float* Wq   = (const float*)d_in[4];
    const float* Wk   = (const float*)d_in[5];
    const float* Wv   = (const float*)d_in[6];
    const float* Wkg  = (const float*)d_in[7];
    const float* Wvg  = (const float*)d_in[8];
    const float* Wkl  = (const float*)d_in[9];
    const float* Wvl  = (const float*)d_in[10];
    const float* Wout = (const float*)d_in[11];
    const float* bout = (const float*)d_in[12];
    const int*   lidx = (const int*)d_in[13];
    float* out = (float*)d_out;

    __half *hsH, *ctxH, *lfH, *WqT, *WkT, *WvT, *WkgT, *WvgT, *WklT, *WvlT, *WoutT;
    __half *vp, *vTp, *vlp, *vlTp;
    cudaGetSymbolAddress((void**)&hsH, g_hsH);
    cudaGetSymbolAddress((void**)&ctxH, g_ctxH);
    cudaGetSymbolAddress((void**)&lfH, g_lfH);
    cudaGetSymbolAddress((void**)&WqT, g_WqT);
    cudaGetSymbolAddress((void**)&WkT, g_WkT);
    cudaGetSymbolAddress((void**)&WvT, g_WvT);
    cudaGetSymbolAddress((void**)&WkgT, g_WkgT);
    cudaGetSymbolAddress((void**)&WvgT, g_WvgT);
    cudaGetSymbolAddress((void**)&WklT, g_WklT);
    cudaGetSymbolAddress((void**)&WvlT, g_WvlT);
    cudaGetSymbolAddress((void**)&WoutT, g_WoutT);
    cudaGetSymbolAddress((void**)&vp, g_v);
    cudaGetSymbolAddress((void**)&vTp, g_vT);
    cudaGetSymbolAddress((void**)&vlp, g_vl);
    cudaGetSymbolAddress((void**)&vlTp, g_vlT);

    const int smemA = (2 * 4096 + 2 * 2048 + 256 * PSTU + 160 * PSTU + 1024) * 4;  // 126,464
    const int smemL = (128 * PLU + 160 * VLU + 512) * 4;                           // 163,840
    cudaFuncSetAttribute(fused_g_k, cudaFuncAttributeMaxDynamicSharedMemorySize, smemA);
    cudaFuncSetAttribute(fused_l2_k, cudaFuncAttributeMaxDynamicSharedMemorySize, smemL);
    cudaFuncSetAttribute(gemm_h, cudaFuncAttributeMaxDynamicSharedMemorySize, SMEM3);

    cudaStream_t sA = g_si.sA, sB = g_si.sB, sC = g_si.sC;
    dim3 tb(32, 8);

    setup_k<<<1, 32>>>(out);
    cudaEventRecord(g_si.evRoot, 0);
    cudaStreamWaitEvent(sA, g_si.evRoot, 0);
    cudaStreamWaitEvent(sB, g_si.evRoot, 0);
    cudaStreamWaitEvent(sC, g_si.evRoot, 0);

    long long nHs = 2LL * SQ * CHN, nCtx = (long long)NST * NCTX * CC, nLf = (long long)NSTR * LLOC * CC;

    // track C: Wq transpose (concurrent with round_h) then Wout transpose
    transpose_k<float><<<dim3(40, 40, 1), tb, 0, sC>>>(Wq, WqT, CHN, CHN, CHN, CHN, 0, 0);
    cudaEventRecord(g_si.evW, sC);
    transpose_k<float><<<dim3(40, 40, 1), tb, 0, sC>>>(Wout, WoutT, CHN, CHN, CHN, CHN, 0, 0);
    cudaEventRecord(g_si.ev3, sC);

    // main track: hs -> Q projection
    round_h<<<(int)((nHs / 8 + 255) / 256), 256>>>(hs, hsH, nHs);
    cudaStreamWaitEvent(0, g_si.evW, 0);
    gemm_h<<<dim3(10, 64, 1), 256, SMEM3>>>(0, CHN, CHN, CHN, CHN, CHN, 1, nullptr);

    // track A: ctx -> K/V/Kg/Vg -> select -> vT
    round_h<<<(int)((nCtx / 8 + 255) / 256), 256, 0, sA>>>(ctx, ctxH, nCtx);
    transpose_k<float><<<dim3(40, 24, 1), tb, 0, sA>>>(Wk, WkT, CC, CHN, CHN, CC, 0, 0);
    transpose_k<float><<<dim3(40, 24, 1), tb, 0, sA>>>(Wv, WvT, CC, CHN, CHN, CC, 0, 0);
    transpose_k<float><<<dim3(40, 24, 1), tb, 0, sA>>>(Wkg, WkgT, CC, CHN, CHN, CC, 0, 0);
    transpose_k<float><<<dim3(40, 24, 1), tb, 0, sA>>>(Wvg, WvgT, CC, CHN, CHN, CC, 0, 0);
    gemm_h<<<dim3(10, 6, 4), 256, SMEM3, sA>>>(1, CHN, CC, CC, CC, CHN, 1, nullptr);
    kv_select_k<<<(NSTR * NCTX * CHN / 2 + 255) / 256, 256, 0, sA>>>(lidx);
    transpose_k<__half><<<dim3(40, 3, NST), tb, 0, sA>>>(vp, vTp, NCTX, CHN, CHN, NCTXP,
                                                         (long long)NCTX * CHN, (long long)CHN * NCTXP);
    cudaEventRecord(g_si.ev1, sA);

    // track B: lf -> Kl/Vl -> vlT
    round_h<<<(int)((nLf / 8 + 255) / 256), 256, 0, sB>>>(lf, lfH, nLf);
    transpose_k<float><<<dim3(40, 24, 1), tb, 0, sB>>>(Wkl, WklT, CC, CHN, CHN, CC, 0, 0);
    transpose_k<float><<<dim3(40, 24, 1), tb, 0, sB>>>(Wvl, WvlT, CC, CHN, CHN, CC, 0, 0);
    gemm_h<<<dim3(10, 17, 2), 256, SMEM3, sB>>>(5, CHN, CC, CC, CC, CHN, 1, nullptr);
    transpose_k<__half><<<dim3(40, 9, NSTR), tb, 0, sB>>>(vlp, vlTp, LLOC, CHN, CHN, LLOCP,
                                                          (long long)LLOC * CHN, (long long)CHN * LLOCP);
    cudaEventRecord(g_si.ev2, sB);

    // global attention (256-row q-tiles, 512 threads)
    cudaStreamWaitEvent(0, g_si.ev1, 0);
    fused_g_k<<<dim3(16, 72), 512, smemA>>>(lidx);
    mmax_k<<<8, 256>>>();
    cudaEventRecord(g_si.evG, 0);

    // uncond out-projection (bias fused) concurrent with local attention
    cudaStreamWaitEvent(sA, g_si.evG, 0);
    cudaStreamWaitEvent(sA, g_si.ev3, 0);
    gemm_h<<<dim3(10, 32, 1), 256, SMEM3, sA>>>(7, CHN, CHN, CHN, CHN, CHN, 4, bout);
    cudaEventRecord(g_si.evO7, sA);

    // local attention (128-row q-tiles)
    cudaStreamWaitEvent(0, g_si.ev2, 0);
    fused_l2_k<<<dim3(32, 64), 256, smemL>>>();

    // premix + cond out-projection (bias+fuser fused)
    premix_k<<<SQ, 256>>>(bbox);
    cudaStreamWaitEvent(0, g_si.ev3, 0);
    gemm_h<<<dim3(10, 32, 1), 256, SMEM3>>>(8, CHN, CHN, CHN, CHN, CHN, 12, bout);

    // join stream A back into the capture-origin stream
    cudaStreamWaitEvent(0, g_si.evO7, 0);
}

// round 17
// speedup vs baseline: 3.3128x; 1.0799x over previous
#include <cuda_runtime.h>
#include <cuda_fp16.h>
#include <math.h>
#include <stdint.h>

#define SQ 4096
#define CHN 1280
#define CC 768
#define NHEAD 8
#define HD 160
#define NCTX 77
#define NCTXP 80
#define NST 9
#define NSTR 8
#define LLOC 257
#define LLOCP 272
#define PSTU 44
#define PCU 180
#define VCU 180
#define SMEM3 (3 * 2048 * 2 * 4)

// ---------------- scratch ----------------
__device__ __align__(256) __half g_hsH[2 * SQ * CHN];
__device__ __align__(256) __half g_ctxH[NST * NCTX * CC];
__device__ __align__(256) __half g_lfH[NSTR * LLOC * CC];
__device__ __align__(256) __half g_q2[2 * SQ * CHN];
__device__ __align__(256) __half g_k[NST * NCTX * CHN];
__device__ __align__(256) __half g_v[NST * NCTX * CHN];
__device__ __align__(256) __half g_kg[NSTR * NCTX * CHN];
__device__ __align__(256) __half g_vg[NSTR * NCTX * CHN];
__device__ __align__(256) __half g_kl[NSTR * LLOC * CHN];
__device__ __align__(256) __half g_vl[NSTR * LLOC * CHN];
__device__ __align__(256) __half g_WqT[CHN * CHN];
__device__ __align__(256) __half g_WkT[CHN * CC];
__device__ __align__(256) __half g_WvT[CHN * CC];
__device__ __align__(256) __half g_WkgT[CHN * CC];
__device__ __align__(256) __half g_WvgT[CHN * CC];
__device__ __align__(256) __half g_WklT[CHN * CC];
__device__ __align__(256) __half g_WvlT[CHN * CC];
__device__ __align__(256) __half g_WoutT[CHN * CHN];
__device__ __align__(256) __half g_vT[NST * CHN * NCTXP];
__device__ __align__(256) __half g_vlT[NSTR * CHN * LLOCP];
__device__ __align__(256) __half g_pre[NST * SQ * CHN];
__device__ __align__(256) __half g_mix[SQ * CHN];
__device__ float g_mraw[NSTR * NHEAD * SQ];
__device__ float g_mmax[NSTR];
__device__ float g_sumw[SQ];

__device__ const __half* d_Ap[16];
__device__ const __half* d_Bp[16];
__device__ void*         d_Cp[16];
__device__ int           d_Mt[16];

// ---------------- streams/events ----------------
struct StreamInit {
    cudaStream_t sA, sB, sC;
    cudaEvent_t evRoot, ev1, ev2, ev3, evG, evO7, evW;
    StreamInit() {
        cudaStreamCreateWithFlags(&sA, cudaStreamNonBlocking);
        cudaStreamCreateWithFlags(&sB, cudaStreamNonBlocking);
        cudaStreamCreateWithFlags(&sC, cudaStreamNonBlocking);
        cudaEventCreateWithFlags(&evRoot, cudaEventDisableTiming);
        cudaEventCreateWithFlags(&ev1, cudaEventDisableTiming);
        cudaEventCreateWithFlags(&ev2, cudaEventDisableTiming);
        cudaEventCreateWithFlags(&ev3, cudaEventDisableTiming);
        cudaEventCreateWithFlags(&evG, cudaEventDisableTiming);
        cudaEventCreateWithFlags(&evO7, cudaEventDisableTiming);
        cudaEventCreateWithFlags(&evW, cudaEventDisableTiming);
    }
};
static StreamInit g_si;

// ---------------- helpers ----------------
__device__ __forceinline__ uint32_t pk2(float a, float b) {
    __half2 h = __halves2half2(__float2half_rn(a), __float2half_rn(b));
    return *(uint32_t*)&h;
}
__device__ __forceinline__ void cp16(void* sdst, const void* gsrc, bool p) {
    uint32_t sa = (uint32_t)__cvta_generic_to_shared(sdst);
    int sz = p ? 16 : 0;
    asm volatile("cp.async.cg.shared.global [%0], [%1], 16, %2;" :: "r"(sa), "l"(gsrc), "r"(sz));
}
#define CP_COMMIT asm volatile("cp.async.commit_group;")
#define CP_WAIT0 asm volatile("cp.async.wait_group 0;")
#define CP_WAIT1 asm volatile("cp.async.wait_group 1;")
__device__ __forceinline__ void mma16(float* c, const uint32_t* a, const uint32_t* b) {
    asm volatile(
        "mma.sync.aligned.m16n8k16.row.col.f32.f16.f16.f32 "
        "{%0,%1,%2,%3}, {%4,%5,%6,%7}, {%8,%9}, {%0,%1,%2,%3};"
        : "+f"(c[0]), "+f"(c[1]), "+f"(c[2]), "+f"(c[3])
        : "r"(a[0]), "r"(a[1]), "r"(a[2]), "r"(a[3]), "r"(b[0]), "r"(b[1]));
}
__device__ __forceinline__ void ldsm4(uint32_t* r, uint32_t addr) {
    asm volatile("ldmatrix.sync.aligned.m8n8.x4.shared.b16 {%0,%1,%2,%3}, [%4];"
                 : "=r"(r[0]), "=r"(r[1]), "=r"(r[2]), "=r"(r[3]) : "r"(addr));
}
__device__ __forceinline__ void ldsm2(uint32_t* r, uint32_t addr) {
    asm volatile("ldmatrix.sync.aligned.m8n8.x2.shared.b16 {%0,%1}, [%2];"
                 : "=r"(r[0]), "=r"(r[1]) : "r"(addr));
}
#define SWOFF(r, c) (((r) << 4) + ((((((c) >> 2) ^ (((r) >> 1) & 3))) << 2) | ((c) & 3)))

// ---------------- setup ----------------
__global__ void setup_k(float* out) {
    if (threadIdx.x == 0) {
        d_Ap[0] = g_hsH;               d_Bp[0] = g_WqT;   d_Cp[0] = g_q2;    d_Mt[0] = 2 * SQ;
        d_Ap[1] = g_ctxH;              d_Bp[1] = g_WkT;   d_Cp[1] = g_k;     d_Mt[1] = NST * NCTX;
        d_Ap[2] = g_ctxH;              d_Bp[2] = g_WvT;   d_Cp[2] = g_v;     d_Mt[2] = NST * NCTX;
        d_Ap[3] = g_ctxH + NCTX * CC;  d_Bp[3] = g_WkgT;  d_Cp[3] = g_kg;    d_Mt[3] = NSTR * NCTX;
        d_Ap[4] = g_ctxH + NCTX * CC;  d_Bp[4] = g_WvgT;  d_Cp[4] = g_vg;    d_Mt[4] = NSTR * NCTX;
        d_Ap[5] = g_lfH;               d_Bp[5] = g_WklT;  d_Cp[5] = g_kl;    d_Mt[5] = NSTR * LLOC;
        d_Ap[6] = g_lfH;               d_Bp[6] = g_WvlT;  d_Cp[6] = g_vl;    d_Mt[6] = NSTR * LLOC;
        d_Ap[7] = g_pre;               d_Bp[7] = g_WoutT; d_Cp[7] = out;     d_Mt[7] = SQ;
        d_Ap[8] = g_mix;               d_Bp[8] = g_WoutT; d_Cp[8] = out + (size_t)SQ * CHN;
        d_Mt[8] = SQ;
    }
}

// ---------------- round inputs to fp16 ----------------
__global__ void round_h(const float* __restrict__ src, __half* __restrict__ dst, long long n) {
    long long i = ((long long)blockIdx.x * blockDim.x + threadIdx.x) * 8;
    if (i + 7 < n) {
        float4 a = *(const float4*)(src + i);
        float4 b = *(const float4*)(src + i + 4);
        uint4 u;
        u.x = pk2(a.x, a.y); u.y = pk2(a.z, a.w);
        u.z = pk2(b.x, b.y); u.w = pk2(b.z, b.w);
        *(uint4*)(dst + i) = u;
    } else {
        for (long long j = i; j < n; j++) dst[j] = __float2half_rn(src[j]);
    }
}

// ---------------- transpose ----------------
template <typename TS>
__global__ void transpose_k(const TS* __restrict__ src, __half* __restrict__ dst,
                            int R, int C, int ldS, int ldD, long long sBS, long long dBS) {
    __shared__ float t[32][33];
    src += blockIdx.z * sBS;
    dst += blockIdx.z * dBS;
    int c0 = blockIdx.x << 5, r0 = blockIdx.y << 5;
    int tx = threadIdx.x, ty = threadIdx.y;
#pragma unroll
    for (int j = 0; j < 4; j++) {
        int rr = r0 + ty + j * 8, cc = c0 + tx;
        t[ty + j * 8][tx] = (rr < R && cc < C) ? (float)src[(size_t)rr * ldS + cc] : 0.f;
    }
    __syncthreads();
#pragma unroll
    for (int j = 0; j < 4; j++) {
        int cc = c0 + ty + j * 8, rr = r0 + tx;
        if (cc < C && rr < ldD)
            dst[(size_t)cc * ldD + rr] = __float2half_rn(t[tx][ty + j * 8]);
    }
}

// ---------------- batched NT fp16 GEMM (R8 core + fused output epilogue) ------
__global__ void __launch_bounds__(256, 2) gemm_h(int slot, int N, int K,
                                                 int lda, int ldb, int ldc, int mode,
                                                 const float* __restrict__ bias) {
    extern __shared__ __align__(16) uint32_t smg[];
    uint32_t* As = smg;
    uint32_t* Bs = smg + 3 * 2048;
    const __half* Ab = d_Ap[slot + blockIdx.z];
    const __half* Bb = d_Bp[slot + blockIdx.z];
    void* Cm         = d_Cp[slot + blockIdx.z];
    const int M      = d_Mt[slot + blockIdx.z];
    int tid = threadIdx.x, lane = tid & 31, warp = tid >> 5;
    int mBase = blockIdx.y << 7, nBase = blockIdx.x << 7;
    int mW = (warp >> 2) << 6, nW = (warp & 3) << 5;
    float acc[4][4][4];
#pragma unroll
    for (int a = 0; a < 4; a++)
#pragma unroll
        for (int b = 0; b < 4; b++)
#pragma unroll
            for (int cI = 0; cI < 4; cI++) acc[a][b][cI] = 0.f;

    int KT = K >> 5;
    auto issue = [&](int st, int kt) {
        int k0 = kt << 5;
#pragma unroll
        for (int i = 0; i < 2; i++) {
            int idx = tid + (i << 8);
            int r = idx >> 2, cu = (idx & 3) << 2;
            int gr = mBase + r; bool pa = gr < M; if (!pa) gr = M - 1;
            cp16(&As[st * 2048 + SWOFF(r, cu)], Ab + (size_t)gr * lda + k0 + (cu << 1), pa);
            int gn = nBase + r; bool pb = gn < N; if (!pb) gn = N - 1;
            cp16(&Bs[st * 2048 + SWOFF(r, cu)], Bb + (size_t)gn * ldb + k0 + (cu << 1), pb);
        }
        CP_COMMIT;
    };
    issue(0, 0);
    issue(1, 1);

    int lrow = lane & 7;
    int lm = lane >> 3;
    int arow[4], axor[4];
#pragma unroll
    for (int mi = 0; mi < 4; mi++) {
        arow[mi] = mW + (mi << 4) + ((lm & 1) << 3) + lrow;
        axor[mi] = (arow[mi] >> 1) & 3;
    }
    int achk = lm >> 1;
    int brow[2], bxor[2];
#pragma unroll
    for (int np = 0; np < 2; np++) {
        brow[np] = nW + (np << 4) + ((lm >> 1) << 3) + lrow;
        bxor[np] = (brow[np] >> 1) & 3;
    }
    int bchk = lm & 1;
    uint32_t sbA = (uint32_t)__cvta_generic_to_shared(As);
    uint32_t sbB = (uint32_t)__cvta_generic_to_shared(Bs);

    for (int kt = 0; kt < KT; kt++) {
        if (kt + 1 < KT) { CP_WAIT1; } else { CP_WAIT0; }
        __syncthreads();
        if (kt + 2 < KT) issue((kt + 2) % 3, kt + 2);
        uint32_t stA = sbA + (kt % 3) * 8192;
        uint32_t stB = sbB + (kt % 3) * 8192;
#pragma unroll
        for (int kk = 0; kk < 2; kk++) {
            uint32_t af[4][4], bf[4][2];
#pragma unroll
            for (int mi = 0; mi < 4; mi++) {
                uint32_t au = (uint32_t)(arow[mi] << 4) + ((((kk << 1) + achk) ^ axor[mi]) << 2);
                ldsm4(af[mi], stA + (au << 2));
            }
#pragma unroll
            for (int np = 0; np < 2; np++) {
                uint32_t bu = (uint32_t)(brow[np] << 4) + ((((kk << 1) + bchk) ^ bxor[np]) << 2);
                uint32_t r4[4];
                ldsm4(r4, stB + (bu << 2));
                bf[np * 2][0] = r4[0]; bf[np * 2][1] = r4[1];
                bf[np * 2 + 1][0] = r4[2]; bf[np * 2 + 1][1] = r4[3];
            }
#pragma unroll
            for (int mi = 0; mi < 4; mi++)
#pragma unroll
                for (int ni = 0; ni < 4; ni++) mma16(acc[mi][ni], af[mi], bf[ni]);
        }
    }
#pragma unroll
    for (int mi = 0; mi < 4; mi++) {
#pragma unroll
        for (int half = 0; half < 2; half++) {
            int gm = mBase + mW + (mi << 4) + (lane >> 2) + half * 8;
            if (gm >= M) continue;
            float sw = 0.f, den = 0.f;
            if (mode & 8) { sw = g_sumw[gm]; den = 1.f / (sw + 1e-6f); }
#pragma unroll
            for (int ni = 0; ni < 4; ni++) {
                int gn = nBase + nW + (ni << 3) + ((lane & 3) << 1);
                if (gn + 1 >= N) continue;
                float v0 = acc[mi][ni][half * 2], v1 = acc[mi][ni][half * 2 + 1];
                if (mode & 1) {
                    __half* crow = (__half*)Cm + (size_t)gm * ldc;
                    *(uint32_t*)(crow + gn) = pk2(v0, v1);
                } else {
                    float* crow = (float*)Cm + (size_t)gm * ldc;
                    if (mode & 4) {
                        float b0 = bias[gn], b1 = bias[gn + 1];
                        if (mode & 8) {
                            v0 = (v0 + b0 * sw) * den;
                            v1 = (v1 + b1 * sw) * den;
                        } else {
                            v0 += b0;
                            v1 += b1;
                        }
                    }
                    crow[gn] = v0;
                    crow[gn + 1] = v1;
                }
            }
        }
    }
}

// ---------------- ELITE K/V select ----------------
__global__ void kv_select_k(const int* __restrict__ lidx) {
    int idx = blockIdx.x * 256 + threadIdx.x;
    const int tot = NSTR * NCTX * CHN / 2;
    if (idx >= tot) return;
    int st = idx / (NCTX * CHN / 2);
    if (lidx[st] >= 0) {
        ((uint32_t*)g_k)[NCTX * CHN / 2 + idx] = ((const uint32_t*)g_kg)[idx];
        ((uint32_t*)g_v)[NCTX * CHN / 2 + idx] = ((const uint32_t*)g_vg)[idx];
    }
}

// ============ fused global attention, STREAM 0 ONLY (256-row q-tiles) ========
// grid (16 qtiles, 8 heads), 512 threads
__global__ void __launch_bounds__(512, 1) fused_g_k(const int* __restrict__ lidx) {
    extern __shared__ __align__(16) uint32_t smu[];
    uint32_t* qb  = smu;
    uint32_t* kb  = smu + 8192;
    uint32_t* psm = smu + 12288;
    uint32_t* vsm = psm + 256 * PSTU;
    float* smx = (float*)(vsm + 160 * PSTU);
    float* ssu = smx + 512;
    __shared__ int sidx[8];

    int h = blockIdx.y;
    int q0 = blockIdx.x << 8;
    int tid = threadIdx.x, lane = tid & 31, warp = tid >> 5;
    if (tid < 8) sidx[tid] = lidx[tid];

    const __half* Qb = g_q2 + (size_t)q0 * CHN + h * HD;
    const __half* Kb = g_k + h * HD;
    const __half* Vt = g_vT + (size_t)h * HD * NCTXP;

    for (int u = tid; u < 160 * 10; u += 512) {
        int d = u / 10, c = u % 10;
        cp16(vsm + d * PSTU + c * 4, Vt + (size_t)d * NCTXP + c * 8, true);
    }
    CP_COMMIT;

    auto issueQK = [&](int st, int kt) {
        int k0 = kt << 5;
#pragma unroll
        for (int i = 0; i < 2; i++) {
            int idx = tid + (i << 9);
            int r = idx >> 2, cu = (idx & 3) << 2;
            cp16(&qb[st * 4096 + SWOFF(r, cu)], Qb + (size_t)r * CHN + k0 + (cu << 1), true);
        }
        {
            int r = tid >> 2, cu = (tid & 3) << 2;
            if (r < 128) {
                int kr = (r < NCTX) ? r : (NCTX - 1);
                cp16(&kb[st * 2048 + SWOFF(r, cu)], Kb + (size_t)kr * CHN + k0 + (cu << 1), true);
            }
        }
        CP_COMMIT;
    };
    issueQK(0, 0);

    int mW = (warp >> 1) << 5;
    int nWs = (warp & 1) * 40;
    int lrow = lane & 7, lm = lane >> 3;
    int aqr[2], aqx[2];
#pragma unroll
    for (int mi = 0; mi < 2; mi++) {
        aqr[mi] = mW + (mi << 4) + ((lm & 1) << 3) + lrow;
        aqx[mi] = (aqr[mi] >> 1) & 3;
    }
    int achk = lm >> 1;
    int bkr[2], bkx[2];
#pragma unroll
    for (int np = 0; np < 2; np++) {
        bkr[np] = nWs + (np << 4) + ((lm >> 1) << 3) + lrow;
        bkx[np] = (bkr[np] >> 1) & 3;
    }
    int bchk = lm & 1;
    int b2r = nWs + 32 + lrow;
    int b2x = (b2r >> 1) & 3;
    int b2c = (lane >> 3) & 1;
    uint32_t sbQ = (uint32_t)__cvta_generic_to_shared(qb);
    uint32_t sbK = (uint32_t)__cvta_generic_to_shared(kb);

    float sc[2][5][4];
#pragma unroll
    for (int a = 0; a < 2; a++)
#pragma unroll
        for (int b = 0; b < 5; b++)
#pragma unroll
            for (int c = 0; c < 4; c++) sc[a][b][c] = 0.f;

    for (int kt = 0; kt < 5; kt++) {
        if (kt < 4) { issueQK((kt + 1) & 1, kt + 1); CP_WAIT1; }
        else        { CP_WAIT0; }
        __syncthreads();
        uint32_t stQ = sbQ + (kt & 1) * 16384;
        uint32_t stK = sbK + (kt & 1) * 8192;
#pragma unroll
        for (int kk = 0; kk < 2; kk++) {
            uint32_t af[2][4], bf[5][2];
#pragma unroll
            for (int mi = 0; mi < 2; mi++) {
                uint32_t au = (uint32_t)(aqr[mi] << 4) + ((((kk << 1) + achk) ^ aqx[mi]) << 2);
                ldsm4(af[mi], stQ + (au << 2));
            }
#pragma unroll
            for (int np = 0; np < 2; np++) {
                uint32_t bu = (uint32_t)(bkr[np] << 4) + ((((kk << 1) + bchk) ^ bkx[np]) << 2);
                uint32_t r4[4];
                ldsm4(r4, stK + (bu << 2));
                bf[np * 2][0] = r4[0]; bf[np * 2][1] = r4[1];
                bf[np * 2 + 1][0] = r4[2]; bf[np * 2 + 1][1] = r4[3];
            }
            {
                uint32_t bu = (uint32_t)(b2r << 4) + ((((kk << 1) + b2c) ^ b2x) << 2);
                uint32_t r2[2];
                ldsm2(r2, stK + (bu << 2));
                bf[4][0] = r2[0]; bf[4][1] = r2[1];
            }
#pragma unroll
            for (int mi = 0; mi < 2; mi++)
#pragma unroll
                for (int ni = 0; ni < 5; ni++) mma16(sc[mi][ni], af[mi], bf[ni]);
        }
        __syncthreads();
    }

    const float scale = 0.07905694150420949f;
    int half = warp & 1;
#pragma unroll
    for (int mi = 0; mi < 2; mi++)
#pragma unroll
        for (int hf = 0; hf < 2; hf++) {
            int row = mW + mi * 16 + (lane >> 2) + hf * 8;
            float mx = -1e30f;
#pragma unroll
            for (int ni = 0; ni < 5; ni++)
#pragma unroll
                for (int c = 0; c < 2; c++) {
                    int col = nWs + ni * 8 + ((lane & 3) << 1) + c;
                    if (col < NCTX) mx = fmaxf(mx, sc[mi][ni][hf * 2 + c]);
                }
            mx = fmaxf(mx, __shfl_xor_sync(0xffffffffu, mx, 1));
            mx = fmaxf(mx, __shfl_xor_sync(0xffffffffu, mx, 2));
            if ((lane & 3) == 0) smx[half * 256 + row] = mx;
        }
    __syncthreads();
#pragma unroll
    for (int mi = 0; mi < 2; mi++)
#pragma unroll
        for (int hf = 0; hf < 2; hf++) {
            int row = mW + mi * 16 + (lane >> 2) + hf * 8;
            float m = fmaxf(smx[row], smx[256 + row]);
            float s = 0.f;
#pragma unroll
            for (int ni = 0; ni < 5; ni++)
#pragma unroll
                for (int c = 0; c < 2; c++) {
                    int col = nWs + ni * 8 + ((lane & 3) << 1) + c;
                    float e = (col < NCTX) ? __expf((sc[mi][ni][hf * 2 + c] - m) * scale) : 0.f;
                    sc[mi][ni][hf * 2 + c] = e;
                    s += e;
                }
            s += __shfl_xor_sync(0xffffffffu, s, 1);
            s += __shfl_xor_sync(0xffffffffu, s, 2);
            if ((lane & 3) == 0) ssu[half * 256 + row] = s;
        }
    __syncthreads();
#pragma unroll
    for (int mi = 0; mi < 2; mi++)
#pragma unroll
        for (int hf = 0; hf < 2; hf++) {
            int row = mW + mi * 16 + (lane >> 2) + hf * 8;
            float inv = 1.f / (ssu[row] + ssu[256 + row]);
#pragma unroll
            for (int ni = 0; ni < 5; ni++) {
                int col = nWs + ni * 8 + ((lane & 3) << 1);
                float v0 = (col < NCTX) ? sc[mi][ni][hf * 2] * inv : 0.f;
                float v1 = (col + 1 < NCTX) ? sc[mi][ni][hf * 2 + 1] * inv : 0.f;
                psm[row * PSTU + (nWs >> 1) + ni * 4 + (lane & 3)] = pk2(v0, v1);
            }
        }
    __syncthreads();

    {
        const __half* ph = (const __half*)psm;
        for (int u = tid; u < 256 * 8; u += 512) {
            int r = u >> 3, i = u & 7;
            g_mraw[((size_t)i * NHEAD + h) * SQ + q0 + r] =
                __half2float(ph[r * (2 * PSTU) + sidx[i]]);
        }
    }

    int nW = (warp & 1) * 80;
    uint32_t sbP = (uint32_t)__cvta_generic_to_shared(psm);
    uint32_t sbV = (uint32_t)__cvta_generic_to_shared(vsm);
    int apr[2];
#pragma unroll
    for (int mi = 0; mi < 2; mi++) apr[mi] = mW + (mi << 4) + ((lm & 1) << 3) + lrow;
    int aco = (lm >> 1) << 2;
    int bvr[5];
#pragma unroll
    for (int np = 0; np < 5; np++) bvr[np] = nW + (np << 4) + ((lm >> 1) << 3) + lrow;
    int bco = (lm & 1) << 2;

    float oa[2][10][4];
#pragma unroll
    for (int a = 0; a < 2; a++)
#pragma unroll
        for (int b = 0; b < 10; b++)
#pragma unroll
            for (int c = 0; c < 4; c++) oa[a][b][c] = 0.f;
#pragma unroll
    for (int kst = 0; kst < 5; kst++) {
        int ka0 = kst * 8;
        uint32_t af[2][4], bf[10][2];
#pragma unroll
        for (int mi = 0; mi < 2; mi++)
            ldsm4(af[mi], sbP + ((uint32_t)(apr[mi] * PSTU + ka0 + aco) << 2));
#pragma unroll
        for (int np = 0; np < 5; np++) {
            uint32_t r4[4];
            ldsm4(r4, sbV + ((uint32_t)(bvr[np] * PSTU + ka0 + bco) << 2));
            bf[np * 2][0] = r4[0]; bf[np * 2][1] = r4[1];
            bf[np * 2 + 1][0] = r4[2]; bf[np * 2 + 1][1] = r4[3];
        }
#pragma unroll
        for (int mi = 0; mi < 2; mi++)
#pragma unroll
            for (int ni = 0; ni < 10; ni++) mma16(oa[mi][ni], af[mi], bf[ni]);
    }
#pragma unroll
    for (int mi = 0; mi < 2; mi++)
#pragma unroll
        for (int hf = 0; hf < 2; hf++) {
            int g = q0 + mW + mi * 16 + (lane >> 2) + hf * 8;
            __half* orow = g_pre + (size_t)g * CHN + h * HD;
#pragma unroll
            for (int ni = 0; ni < 10; ni++) {
                int col = nW + (ni << 3) + ((lane & 3) << 1);
                *(uint32_t*)(orow + col) = pk2(oa[mi][ni][hf * 2], oa[mi][ni][hf * 2 + 1]);
            }
        }
}

// ---------------- per-instance gate max ----------------
__global__ void mmax_k() {
    __shared__ float red[256];
    int i = blockIdx.x;
    float mx = 0.f;
    const float* p = g_mraw + (size_t)i * NHEAD * SQ;
    for (int idx = threadIdx.x; idx < NHEAD * SQ; idx += 256) mx = fmaxf(mx, p[idx]);
    red[threadIdx.x] = mx;
    __syncthreads();
    for (int s = 128; s > 0; s >>= 1) {
        if (threadIdx.x < s) red[threadIdx.x] = fmaxf(red[threadIdx.x], red[threadIdx.x + s]);
        __syncthreads();
    }
    if (threadIdx.x == 0) g_mmax[i] = red[0];
}

// ============ merged cond attention: global + local in one block ============
// grid (32 qtiles of 128 rows, 64 inst*8+h), 256 threads.
// P columns (u32): [0..40) global probs * 0.5/s_g ; [40..176) local probs * gate.
// V columns     : [0..40) global V^T ; [40..176) local V^T. One PV over 352 keys.
__global__ void __launch_bounds__(256) fused_l2_k() {
    extern __shared__ __align__(16) uint32_t smu[];
    uint32_t* plm = smu;                               // 128 * PCU
    uint32_t* vsm = smu + 128 * PCU;                   // 160 * VCU (aliases staging)
    float* smx = (float*)(smu + 128 * PCU + 160 * VCU);
    float* ssu = smx + 256;

    int z = blockIdx.y;
    int inst = z >> 3, h = z & 7;
    int q0 = blockIdx.x << 7;
    int tid = threadIdx.x, lane = tid & 31, warp = tid >> 5;

    const __half* Qb  = g_q2 + (size_t)SQ * CHN + (size_t)q0 * CHN + h * HD;
    const __half* Klb = g_kl + (size_t)inst * LLOC * CHN + h * HD;
    const __half* Kgb = g_k + (size_t)(inst + 1) * NCTX * CHN + h * HD;
    const __half* VtL = g_vlT + (size_t)inst * CHN * LLOCP + (size_t)h * HD * LLOCP;
    const __half* VtG = g_vT + (size_t)(inst + 1) * CHN * NCTXP + (size_t)h * HD * NCTXP;

    uint32_t* strm = vsm;
    const float scale = 0.07905694150420949f;
    int lrow = lane & 7, lm = lane >> 3;
    int mW2 = (warp >> 1) << 5;
    int aqr[2], aqx[2];
#pragma unroll
    for (int mi = 0; mi < 2; mi++) {
        aqr[mi] = mW2 + (mi << 4) + ((lm & 1) << 3) + lrow;
        aqx[mi] = (aqr[mi] >> 1) & 3;
    }
    int achk = lm >> 1;
    int bchk = lm & 1;
    uint32_t sbS = (uint32_t)__cvta_generic_to_shared(strm);

    // ================= PHASE A: local scores =================
    auto issueL = [&](int st, int kt) {
        int k0 = kt << 5;
        uint32_t* base = strm + st * 6656;
#pragma unroll
        for (int i = 0; i < 2; i++) {
            int idx = tid + (i << 8);
            int r = idx >> 2, cu = (idx & 3) << 2;
            cp16(base + SWOFF(r, cu), Qb + (size_t)r * CHN + k0 + (cu << 1), true);
        }
        for (int u = tid; u < 1152; u += 256) {
            int r = u >> 2, cu = (u & 3) << 2;
            int kr = (r < LLOC) ? r : (LLOC - 1);
            cp16(base + 2048 + SWOFF(r, cu), Klb + (size_t)kr * CHN + k0 + (cu << 1), true);
        }
        CP_COMMIT;
    };
    issueL(0, 0);

    int nW4 = (warp & 1) * 144;
    {
        int bkr[9], bkx[9];
#pragma unroll
        for (int np = 0; np < 9; np++) {
            bkr[np] = nW4 + (np << 4) + ((lm >> 1) << 3) + lrow;
            bkx[np] = (bkr[np] >> 1) & 3;
        }
        float sc[2][18][4];
#pragma unroll
        for (int a = 0; a < 2; a++)
#pragma unroll
            for (int b = 0; b < 18; b++)
#pragma unroll
                for (int c = 0; c < 4; c++) sc[a][b][c] = 0.f;

        for (int kt = 0; kt < 5; kt++) {
            if (kt < 4) { issueL((kt + 1) & 1, kt + 1); CP_WAIT1; }
            else        { CP_WAIT0; }
            __syncthreads();
            uint32_t stQ = sbS + (kt & 1) * 26624;
            uint32_t stK = stQ + 8192;
#pragma unroll
            for (int kk = 0; kk < 2; kk++) {
                uint32_t af[2][4], bf[18][2];
#pragma unroll
                for (int mi = 0; mi < 2; mi++) {
                    uint32_t au = (uint32_t)(aqr[mi] << 4) + ((((kk << 1) + achk) ^ aqx[mi]) << 2);
                    ldsm4(af[mi], stQ + (au << 2));
                }
#pragma unroll
                for (int np = 0; np < 9; np++) {
                    uint32_t bu = (uint32_t)(bkr[np] << 4) + ((((kk << 1) + bchk) ^ bkx[np]) << 2);
                    uint32_t r4[4];
                    ldsm4(r4, stK + (bu << 2));
                    bf[np * 2][0] = r4[0]; bf[np * 2][1] = r4[1];
                    bf[np * 2 + 1][0] = r4[2]; bf[np * 2 + 1][1] = r4[3];
                }
#pragma unroll
                for (int mi = 0; mi < 2; mi++)
#pragma unroll
                    for (int ni = 0; ni < 18; ni++) mma16(sc[mi][ni], af[mi], bf[ni]);
            }
            __syncthreads();
        }

        // softmax local + gate -> plm cols [40..176)
        float gden = 0.5f / g_mmax[inst];
#pragma unroll
        for (int mi = 0; mi < 2; mi++)
#pragma unroll
            for (int hf = 0; hf < 2; hf++) {
                int row = mW2 + mi * 16 + (lane >> 2) + hf * 8;
                float mx = -1e30f;
#pragma unroll
                for (int ni = 0; ni < 18; ni++)
#pragma unroll
                    for (int c = 0; c < 2; c++) {
                        int col = nW4 + ni * 8 + ((lane & 3) << 1) + c;
                        if (col < LLOC) mx = fmaxf(mx, sc[mi][ni][hf * 2 + c]);
                    }
                mx = fmaxf(mx, __shfl_xor_sync(0xffffffffu, mx, 1));
                mx = fmaxf(mx, __shfl_xor_sync(0xffffffffu, mx, 2));
                if ((lane & 3) == 0) smx[row * 2 + (warp & 1)] = mx;
            }
        __syncthreads();
#pragma unroll
        for (int mi = 0; mi < 2; mi++)
#pragma unroll
            for (int hf = 0; hf < 2; hf++) {
                int row = mW2 + mi * 16 + (lane >> 2) + hf * 8;
                float m = fmaxf(smx[row * 2], smx[row * 2 + 1]);
                float s = 0.f;
#pragma unroll
                for (int ni = 0; ni < 18; ni++)
#pragma unroll
                    for (int c = 0; c < 2; c++) {
                        int col = nW4 + ni * 8 + ((lane & 3) << 1) + c;
                        float e = (col < LLOC) ? __expf((sc[mi][ni][hf * 2 + c] - m) * scale) : 0.f;
                        sc[mi][ni][hf * 2 + c] = e;
                        s += e;
                    }
                s += __shfl_xor_sync(0xffffffffu, s, 1);
                s += __shfl_xor_sync(0xffffffffu, s, 2);
                if ((lane & 3) == 0) ssu[row * 2 + (warp & 1)] = s;
            }
        __syncthreads();
#pragma unroll
        for (int mi = 0; mi < 2; mi++)
#pragma unroll
            for (int hf = 0; hf < 2; hf++) {
                int row = mW2 + mi * 16 + (lane >> 2) + hf * 8;
                float s = ssu[row * 2] + ssu[row * 2 + 1];
                float f = g_mraw[(size_t)z * SQ + q0 + row] * gden / s;
#pragma unroll
                for (int ni = 0; ni < 18; ni++) {
                    int ucol = (nW4 >> 1) + ni * 4 + (lane & 3);
                    if (ucol < 136)
                        plm[row * PCU + 40 + ucol] = pk2(sc[mi][ni][hf * 2] * f, sc[mi][ni][hf * 2 + 1] * f);
                }
            }
        __syncthreads();   // staging reads done; partials free for phase B
    }

    // ================= PHASE B: global scores (77 keys) =================
    auto issueG = [&](int st, int kt) {
        int k0 = kt << 5;
        uint32_t* base = strm + st * 4096;
#pragma unroll
        for (int i = 0; i < 2; i++) {
            int idx = tid + (i << 8);
            int r = idx >> 2, cu = (idx & 3) << 2;
            cp16(base + SWOFF(r, cu), Qb + (size_t)r * CHN + k0 + (cu << 1), true);
            int kr = (r < NCTX) ? r : (NCTX - 1);
            cp16(base + 2048 + SWOFF(r, cu), Kgb + (size_t)kr * CHN + k0 + (cu << 1), true);
        }
        CP_COMMIT;
    };
    issueG(0, 0);

    int nWs = (warp & 1) * 40;
    {
        int bkr[2], bkx[2];
#pragma unroll
        for (int np = 0; np < 2; np++) {
            bkr[np] = nWs + (np << 4) + ((lm >> 1) << 3) + lrow;
            bkx[np] = (bkr[np] >> 1) & 3;
        }
        int b2r = nWs + 32 + lrow;
        int b2x = (b2r >> 1) & 3;
        int b2c = (lane >> 3) & 1;

        float sg[2][5][4];
#pragma unroll
        for (int a = 0; a < 2; a++)
#pragma unroll
            for (int b = 0; b < 5; b++)
#pragma unroll
                for (int c = 0; c < 4; c++) sg[a][b][c] = 0.f;

        for (int kt = 0; kt < 5; kt++) {
            if (kt < 4) { issueG((kt + 1) & 1, kt + 1); CP_WAIT1; }
            else        { CP_WAIT0; }
            __syncthreads();
            uint32_t stQ = sbS + (kt & 1) * 16384;
            uint32_t stK = stQ + 8192;
#pragma unroll
            for (int kk = 0; kk < 2; kk++) {
                uint32_t af[2][4], bf[5][2];
#pragma unroll
                for (int mi = 0; mi < 2; mi++) {
                    uint32_t au = (uint32_t)(aqr[mi] << 4) + ((((kk << 1) + achk) ^ aqx[mi]) << 2);
                    ldsm4(af[mi], stQ + (au << 2));
                }
#pragma unroll
                for (int np = 0; np < 2; np++) {
                    uint32_t bu = (uint32_t)(bkr[np] << 4) + ((((kk << 1) + bchk) ^ bkx[np]) << 2);
                    uint32_t r4[4];
                    ldsm4(r4, stK + (bu << 2));
                    bf[np * 2][0] = r4[0]; bf[np * 2][1] = r4[1];
                    bf[np * 2 + 1][0] = r4[2]; bf[np * 2 + 1][1] = r4[3];
                }
                {
                    uint32_t bu = (uint32_t)(b2r << 4) + ((((kk << 1) + b2c) ^ b2x) << 2);
                    uint32_t r2[2];
                    ldsm2(r2, stK + (bu << 2));
                    bf[4][0] = r2[0]; bf[4][1] = r2[1];
                }
#pragma unroll
                for (int mi = 0; mi < 2; mi++)
#pragma unroll
                    for (int ni = 0; ni < 5; ni++) mma16(sg[mi][ni], af[mi], bf[ni]);
            }
            __syncthreads();
        }

        // issue V loads (global + local) into vsm — overwrites staging
        for (int u = tid; u < 160 * 44; u += 256) {
            int d = u / 44, c = u % 44;
            if (c < 10)
                cp16(vsm + d * VCU + c * 4, VtG + (size_t)d * NCTXP + c * 8, true);
            else
                cp16(vsm + d * VCU + 40 + (c - 10) * 4, VtL + (size_t)d * LLOCP + (c - 10) * 8, true);
        }
        CP_COMMIT;

        // softmax global, scaled by 0.5, -> plm cols [0..40)
#pragma unroll
        for (int mi = 0; mi < 2; mi++)
#pragma unroll
            for (int hf = 0; hf < 2; hf++) {
                int row = mW2 + mi * 16 + (lane >> 2) + hf * 8;
                float mx = -1e30f;
#pragma unroll
                for (int ni = 0; ni < 5; ni++)
#pragma unroll
                    for (int c = 0; c < 2; c++) {
                        int col = nWs + ni * 8 + ((lane & 3) << 1) + c;
                        if (col < NCTX) mx = fmaxf(mx, sg[mi][ni][hf * 2 + c]);
                    }
                mx = fmaxf(mx, __shfl_xor_sync(0xffffffffu, mx, 1));
                mx = fmaxf(mx, __shfl_xor_sync(0xffffffffu, mx, 2));
                if ((lane & 3) == 0) smx[row * 2 + (warp & 1)] = mx;
            }
        __syncthreads();
#pragma unroll
        for (int mi = 0; mi < 2; mi++)
#pragma unroll
            for (int hf = 0; hf < 2; hf++) {
                int row = mW2 + mi * 16 + (lane >> 2) + hf * 8;
                float m = fmaxf(smx[row * 2], smx[row * 2 + 1]);
                float s = 0.f;
#pragma unroll
                for (int ni = 0; ni < 5; ni++)
#pragma unroll
                    for (int c = 0; c < 2; c++) {
                        int col = nWs + ni * 8 + ((lane & 3) << 1) + c;
                        float e = (col < NCTX) ? __expf((sg[mi][ni][hf * 2 + c] - m) * scale) : 0.f;
                        sg[mi][ni][hf * 2 + c] = e;
                        s += e;
                    }
                s += __shfl_xor_sync(0xffffffffu, s, 1);
                s += __shfl_xor_sync(0xffffffffu, s, 2);
                if ((lane & 3) == 0) ssu[row * 2 + (warp & 1)] = s;
            }
        __syncthreads();
#pragma unroll
        for (int mi = 0; mi < 2; mi++)
#pragma unroll
            for (int hf = 0; hf < 2; hf++) {
                int row = mW2 + mi * 16 + (lane >> 2) + hf * 8;
                float inv = 0.5f / (ssu[row * 2] + ssu[row * 2 + 1]);
#pragma unroll
                for (int ni = 0; ni < 5; ni++) {
                    int col = nWs + ni * 8 + ((lane & 3) << 1);
                    float v0 = (col < NCTX) ? sg[mi][ni][hf * 2] * inv : 0.f;
                    float v1 = (col + 1 < NCTX) ? sg[mi][ni][hf * 2 + 1] * inv : 0.f;
                    plm[row * PCU + (nWs >> 1) + ni * 4 + (lane & 3)] = pk2(v0, v1);
                }
            }
    }
    CP_WAIT0;
    __syncthreads();   // plm complete + V resident

    // ================= PHASE C: PV over 352 keys =================
    int nW = (warp & 1) * 80;
    uint32_t sbP = (uint32_t)__cvta_generic_to_shared(plm);
    uint32_t sbV = (uint32_t)__cvta_generic_to_shared(vsm);
    int apr[2];
#pragma unroll
    for (int mi = 0; mi < 2; mi++) apr[mi] = mW2 + (mi << 4) + ((lm & 1) << 3) + lrow;
    int aco = (lm >> 1) << 2;
    int bvr[5];
#pragma unroll
    for (int np = 0; np < 5; np++) bvr[np] = nW + (np << 4) + ((lm >> 1) << 3) + lrow;
    int bco = (lm & 1) << 2;

    float oa[2][10][4];
#pragma unroll
    for (int a = 0; a < 2; a++)
#pragma unroll
        for (int b = 0; b < 10; b++)
#pragma unroll
            for (int c = 0; c < 4; c++) oa[a][b][c] = 0.f;

#pragma unroll 1
    for (int ch = 0; ch < 22; ch++) {
        int ka0 = ch * 8;
        uint32_t af[2][4], bf[10][2];
#pragma unroll
        for (int mi = 0; mi < 2; mi++)
            ldsm4(af[mi], sbP + ((uint32_t)(apr[mi] * PCU + ka0 + aco) << 2));
#pragma unroll
        for (int np = 0; np < 5; np++) {
            uint32_t r4[4];
            ldsm4(r4, sbV + ((uint32_t)(bvr[np] * VCU + ka0 + bco) << 2));
            bf[np * 2][0] = r4[0]; bf[np * 2][1] = r4[1];
            bf[np * 2 + 1][0] = r4[2]; bf[np * 2 + 1][1] = r4[3];
        }
#pragma unroll
        for (int mi = 0; mi < 2; mi++)
#pragma unroll
            for (int ni = 0; ni < 10; ni++) mma16(oa[mi][ni], af[mi], bf[ni]);
    }

    // epilogue: pre[inst+1] = O (final; no blend read)
#pragma unroll
    for (int mi = 0; mi < 2; mi++)
#pragma unroll
        for (int hf = 0; hf < 2; hf++) {
            int g = q0 + mW2 + mi * 16 + (lane >> 2) + hf * 8;
            __half* prow = g_pre + ((size_t)(inst + 1) * SQ + g) * CHN + h * HD;
#pragma unroll
            for (int ni = 0; ni < 10; ni++) {
                int col = nW + (ni << 3) + ((lane & 3) << 1);
                *(uint32_t*)(prow + col) = pk2(oa[mi][ni][hf * 2], oa[mi][ni][hf * 2 + 1]);
            }
        }
}

// ---------------- fuser premix ----------------
__global__ void premix_k(const float* __restrict__ bbox) {
    int s = blockIdx.x;
    int y = s >> 6, x = s & 63;
    float wgt[8];
    wgt[0] = 1.f;
    float sw = 1.f;
    const int off[4] = {3, 4, 11, 12};
#pragma unroll
    for (int i = 0; i < 7; i++) {
        float wmin = floorf(1024.f * bbox[i * 4 + 0]);
        float hmin = floorf(1024.f * bbox[i * 4 + 1]);
        float wmax = floorf(1024.f * bbox[i * 4 + 2]);
        float hmax = floorf(1024.f * bbox[i * 4 + 3]);
        float R = 0.f, Cv = 0.f;
#pragma unroll
        for (int j = 0; j < 4; j++) {
            float yy = (float)(16 * y + off[j]);
            float xx = (float)(16 * x + off[j]);
            if (yy >= hmin && yy < hmax) R += 0.25f;
            if (xx >= wmin && xx < wmax) Cv += 0.25f;
        }
        float g = 10.f * R * Cv;
        wgt[i + 1] = g;
        sw += g;
    }
    if (threadIdx.x == 0) g_sumw[s] = sw;
    for (int c = threadIdx.x; c < CHN; c += 256) {
        float acc = 0.f;
#pragma unroll
        for (int j = 0; j < 8; j++)
            acc += wgt[j] * __half2float(g_pre[((size_t)(1 + j) * SQ + s) * CHN + c]);
        g_mix[(size_t)s * CHN + c] = __float2half_rn(acc);
    }
}

// ---------------- launch ----------------
extern "C" void kernel_launch(void* const* d_in, const int* in_sizes, int n_in,
                              void* d_out, int out_size) {
    const float* hs   = (const float*)d_in[0];
    const float* ctx  = (const float*)d_in[1];
    const float* lf   = (const float*)d_in[2];
    const float* bbox = (const float*)d_in[3];
    const float* Wq   = (const float*)d_in[4];
    const float* Wk   = (const float*)d_in[5];
    const float* Wv   = (const float*)d_in[6];
    const float* Wkg  = (const float*)d_in[7];
    const float* Wvg  = (const float*)d_in[8];
    const float* Wkl  = (const float*)d_in[9];
    const float* Wvl  = (const float*)d_in[10];
    const float* Wout = (const float*)d_in[11];
    const float* bout = (const float*)d_in[12];
    const int*   lidx = (const int*)d_in[13];
    float* out = (float*)d_out;

    __half *hsH, *ctxH, *lfH, *WqT, *WkT, *WvT, *WkgT, *WvgT, *WklT, *WvlT, *WoutT;
    __half *vp, *vTp, *vlp, *vlTp;
    cudaGetSymbolAddress((void**)&hsH, g_hsH);
    cudaGetSymbolAddress((void**)&ctxH, g_ctxH);
    cudaGetSymbolAddress((void**)&lfH, g_lfH);
    cudaGetSymbolAddress((void**)&WqT, g_WqT);
    cudaGetSymbolAddress((void**)&WkT, g_WkT);
    cudaGetSymbolAddress((void**)&WvT, g_WvT);
    cudaGetSymbolAddress((void**)&WkgT, g_WkgT);
    cudaGetSymbolAddress((void**)&WvgT, g_WvgT);
    cudaGetSymbolAddress((void**)&WklT, g_WklT);
    cudaGetSymbolAddress((void**)&WvlT, g_WvlT);
    cudaGetSymbolAddress((void**)&WoutT, g_WoutT);
    cudaGetSymbolAddress((void**)&vp, g_v);
    cudaGetSymbolAddress((void**)&vTp, g_vT);
    cudaGetSymbolAddress((void**)&vlp, g_vl);
    cudaGetSymbolAddress((void**)&vlTp, g_vlT);

    const int smemA = (2 * 4096 + 2 * 2048 + 256 * PSTU + 160 * PSTU + 1024) * 4;
    const int smemL = (128 * PCU + 160 * VCU + 512) * 4;   // 209,408
    cudaFuncSetAttribute(fused_g_k, cudaFuncAttributeMaxDynamicSharedMemorySize, smemA);
    cudaFuncSetAttribute(fused_l2_k, cudaFuncAttributeMaxDynamicSharedMemorySize, smemL);
    cudaFuncSetAttribute(gemm_h, cudaFuncAttributeMaxDynamicSharedMemorySize, SMEM3);

    cudaStream_t sA = g_si.sA, sB = g_si.sB, sC = g_si.sC;
    dim3 tb(32, 8);

    setup_k<<<1, 32>>>(out);
    cudaEventRecord(g_si.evRoot, 0);
    cudaStreamWaitEvent(sA, g_si.evRoot, 0);
    cudaStreamWaitEvent(sB, g_si.evRoot, 0);
    cudaStreamWaitEvent(sC, g_si.evRoot, 0);

    long long nHs = 2LL * SQ * CHN, nCtx = (long long)NST * NCTX * CC, nLf = (long long)NSTR * LLOC * CC;

    // track C: Wq transpose (concurrent with round_h) then Wout transpose
    transpose_k<float><<<dim3(40, 40, 1), tb, 0, sC>>>(Wq, WqT, CHN, CHN, CHN, CHN, 0, 0);
    cudaEventRecord(g_si.evW, sC);
    transpose_k<float><<<dim3(40, 40, 1), tb, 0, sC>>>(Wout, WoutT, CHN, CHN, CHN, CHN, 0, 0);
    cudaEventRecord(g_si.ev3, sC);

    // main track: hs -> Q projection
    round_h<<<(int)((nHs / 8 + 255) / 256), 256>>>(hs, hsH, nHs);
    cudaStreamWaitEvent(0, g_si.evW, 0);
    gemm_h<<<dim3(10, 64, 1), 256, SMEM3>>>(0, CHN, CHN, CHN, CHN, CHN, 1, nullptr);

    // track A: ctx -> K/V/Kg/Vg -> select -> vT
    round_h<<<(int)((nCtx / 8 + 255) / 256), 256, 0, sA>>>(ctx, ctxH, nCtx);
    transpose_k<float><<<dim3(40, 24, 1), tb, 0, sA>>>(Wk, WkT, CC, CHN, CHN, CC, 0, 0);
    transpose_k<float><<<dim3(40, 24, 1), tb, 0, sA>>>(Wv, WvT, CC, CHN, CHN, CC, 0, 0);
    transpose_k<float><<<dim3(40, 24, 1), tb, 0, sA>>>(Wkg, WkgT, CC, CHN, CHN, CC, 0, 0);
    transpose_k<float><<<dim3(40, 24, 1), tb, 0, sA>>>(Wvg, WvgT, CC, CHN, CHN, CC, 0, 0);
    gemm_h<<<dim3(10, 6, 4), 256, SMEM3, sA>>>(1, CHN, CC, CC, CC, CHN, 1, nullptr);
    kv_select_k<<<(NSTR * NCTX * CHN / 2 + 255) / 256, 256, 0, sA>>>(lidx);
    transpose_k<__half><<<dim3(40, 3, NST), tb, 0, sA>>>(vp, vTp, NCTX, CHN, CHN, NCTXP,
                                                         (long long)NCTX * CHN, (long long)CHN * NCTXP);
    cudaEventRecord(g_si.ev1, sA);

    // track B: lf -> Kl/Vl -> vlT
    round_h<<<(int)((nLf / 8 + 255) / 256), 256, 0, sB>>>(lf, lfH, nLf);
    transpose_k<float><<<dim3(40, 24, 1), tb, 0, sB>>>(Wkl, WklT, CC, CHN, CHN, CC, 0, 0);
    transpose_k<float><<<dim3(40, 24, 1), tb, 0, sB>>>(Wvl, WvlT, CC, CHN, CHN, CC, 0, 0);
    gemm_h<<<dim3(10, 17, 2), 256, SMEM3, sB>>>(5, CHN, CC, CC, CC, CHN, 1, nullptr);
    transpose_k<__half><<<dim3(40, 9, NSTR), tb, 0, sB>>>(vlp, vlTp, LLOC, CHN, CHN, LLOCP,
                                                          (long long)LLOC * CHN, (long long)CHN * LLOCP);
    cudaEventRecord(g_si.ev2, sB);

    // global attention, stream 0 only -> pre[0] + mraw
    cudaStreamWaitEvent(0, g_si.ev1, 0);
    fused_g_k<<<dim3(16, 8), 512, smemA>>>(lidx);
    mmax_k<<<8, 256>>>();
    cudaEventRecord(g_si.evG, 0);

    // uncond out-projection (bias fused) concurrent with merged cond attention
    cudaStreamWaitEvent(sA, g_si.evG, 0);
    cudaStreamWaitEvent(sA, g_si.ev3, 0);
    gemm_h<<<dim3(10, 32, 1), 256, SMEM3, sA>>>(7, CHN, CHN, CHN, CHN, CHN, 4, bout);
    cudaEventRecord(g_si.evO7, sA);

    // merged cond attention (global + local + blend) -> pre[1..8]
    cudaStreamWaitEvent(0, g_si.ev2, 0);
    fused_l2_k<<<dim3(32, 64), 256, smemL>>>();

    // premix + cond out-projection (bias+fuser fused)
    premix_k<<<SQ, 256>>>(bbox);
    cudaStreamWaitEvent(0, g_si.ev3, 0);
    gemm_h<<<dim3(10, 32, 1), 256, SMEM3>>>(8, CHN, CHN, CHN, CHN, CHN, 12, bout);

    // join stream A back into the capture-origin stream
    cudaStreamWaitEvent(0, g_si.evO7, 0);
}